// round 16
// baseline (speedup 1.0000x reference)
#include <cuda_runtime.h>
#include <cstdint>

#define V 8192
#define NB 64
#define M3 24576
#define STRIDE 8194
#define MT 256
#define NTILE 96             // 24576 / 256 m-tiles
#define KS 32                // split-K -> 256 K per unit
#define NUNITS (NTILE * KS)  // 3072
#define GRID 296             // persistent, 2 CTAs/SM
#define KC 16                // k rows per stage (1KB-wide rows)
#define SPU 16               // stages per unit (256/16)
#define NST 3                // cp.async ring depth

#define PC 260               // C pitch: 2-row stride 520%32=8 -> conflict-free frags
#define PFW 72               // f pair-tile pitch (words)
#define PD 72

#define CS_FLOATS (KC * PC)                  // 4160
#define FS_WORDS  (8 * PFW)                  // 576 (8 k2-rows)
#define SB_FLOATS (CS_FLOATS + FS_WORDS)     // 4736
#define SB_BYTES  (SB_FLOATS * 4)            // 18944
#define DS_OFF    (NST * SB_FLOATS)          // 14208 floats
#define SOUT_OFF  (DS_OFF + 64 * PD)         // 18816
#define SMEM_DYN  ((SOUT_OFF + 192) * 4)     // 76032 B -> 2 CTAs/SM

#define MMA_BF16(d, a0, a1, a2, a3, b0, b1)                                   \
    asm volatile("mma.sync.aligned.m16n8k16.row.col.f32.bf16.bf16.f32 "       \
        "{%0,%1,%2,%3}, {%4,%5,%6,%7}, {%8,%9}, {%0,%1,%2,%3};"               \
        : "+f"((d)[0]), "+f"((d)[1]), "+f"((d)[2]), "+f"((d)[3])              \
        : "r"(a0), "r"(a1), "r"(a2), "r"(a3), "r"(b0), "r"(b1))

#define CP16(dst_u32, src_gl) \
    asm volatile("cp.async.cg.shared.global [%0], [%1], 16;" :: "r"(dst_u32), "l"(src_gl))
#define CP_COMMIT()  asm volatile("cp.async.commit_group;" ::: "memory")
#define CP_WAIT1()   asm volatile("cp.async.wait_group 1;" ::: "memory")

// f packed as bf16 k-pairs: g_fP[i2*64 + b] = {lo: f[b][2*i2], hi: f[b][2*i2+1]}
__device__ unsigned g_fP[(V / 2) * NB];   // 1 MB, L2-resident

__device__ __forceinline__ unsigned pack_bf16(float lo, float hi) {
    unsigned r;
    asm("cvt.rn.bf16x2.f32 %0, %1, %2;" : "=r"(r) : "f"(hi), "f"(lo));
    return r;
}

// ---------------------------------------------------------------------------
__global__ void prep_kernel(const float* __restrict__ func, float* __restrict__ out) {
    int idx = blockIdx.x * 256 + threadIdx.x;    // < (V/2)*NB = 262144
    int i2 = idx >> 6;
    int b  = idx & 63;
    float lo = func[b * STRIDE + 2 * i2];
    float hi = func[b * STRIDE + 2 * i2 + 1];
    g_fP[idx] = pack_bf16(lo, hi);
    if (idx < NB) {
        const float QI = 1000000000.0f;
        float a1 = func[idx * STRIDE + V];
        float a2 = func[idx * STRIDE + V + 1];
        out[idx * 3 + 0] = a1 * -QI;
        out[idx * 3 + 1] = (1.0f - (1.0f - a1) * (1.0f - a2)) * -QI;
        out[idx * 3 + 2] = 0.0f;
    }
}

// ---------------------------------------------------------------------------
// Persistent bf16 mma.sync GEMM: 256-wide m-tiles (1KB DRAM row segments),
// 8 m-group warps x full-K, 2 CTAs/SM, 3-deep cp.async ring.
// ---------------------------------------------------------------------------
__global__ __launch_bounds__(256, 2)
void cooc_mma(const float* __restrict__ cooc,
              const float* __restrict__ arg,
              float* __restrict__ out) {
    extern __shared__ float sm[];
    float* Ds   = sm + DS_OFF;      // 64 rows x PD (two mg-slabs per pass)
    float* sout = sm + SOUT_OFF;

    const int tid  = threadIdx.x;
    const int lane = tid & 31;
    const int mg   = tid >> 5;         // m-group: 32 m each (8 groups)
    const int quad = lane & 3;
    const int qid  = lane >> 2;
    const int bid  = blockIdx.x;

    const int nu    = 1 + (NUNITS - 1 - bid) / GRID;
    const int total = nu * SPU;

    unsigned smem_base;
    asm("{ .reg .u64 t; cvta.to.shared.u64 t, %1; cvt.u32.u64 %0, t; }"
        : "=r"(smem_base) : "l"(sm));

    const char* cooc_g = (const char*)__cvta_generic_to_global(cooc);
    const char* fP_g   = (const char*)__cvta_generic_to_global(g_fP);

    // -------- incremental issue-stream state ----
    int u_i  = bid;
    int sl_i = 0;
    int m0_i, k0_i;
    {
        int ks = u_i / NTILE;
        m0_i = (u_i - ks * NTILE) * MT;
        k0_i = ks * (V / KS);
    }
    int slot_i = 0;

    auto issue = [&]() {
        unsigned buf = smem_base + (unsigned)(slot_i * SB_BYTES);
        // C: 16 rows x 1KB = 1024 chunks -> 4 per thread
        #pragma unroll
        for (int it = 0; it < 4; it++) {
            int flat = it * 256 + tid;
            int row = flat >> 6, c16 = flat & 63;
            const char* src = cooc_g + ((size_t)(k0_i + row) * M3 + m0_i + c16 * 4) * 4;
            CP16(buf + (unsigned)(row * PC + c16 * 4) * 4, src);
        }
        // f: 8 k2-rows x 64 words = 128 chunks -> half the threads
        if (tid < 128) {
            int row = tid >> 4, c16 = tid & 15;
            const char* src = fP_g + ((size_t)((k0_i >> 1) + row) * 64 + c16 * 4) * 4;
            CP16(buf + CS_FLOATS * 4 + (unsigned)(row * PFW + c16 * 4) * 4, src);
        }
    };
    auto adv = [&]() {
        slot_i = (slot_i == NST - 1) ? 0 : slot_i + 1;
        if (++sl_i == SPU) {
            sl_i = 0;
            u_i += GRID;
            if (u_i < NUNITS) {
                int ks = u_i / NTILE;
                m0_i = (u_i - ks * NTILE) * MT;
                k0_i = ks * (V / KS);
            }
        } else {
            k0_i += KC;
        }
    };

    float acc[2][8][4];
    #pragma unroll
    for (int mt = 0; mt < 2; mt++)
        #pragma unroll
        for (int nt = 0; nt < 8; nt++)
            #pragma unroll
            for (int r = 0; r < 4; r++) acc[mt][nt][r] = 0.0f;

    float po0 = 0.f, po1 = 0.f, po2 = 0.f;
    const int bb = tid & 63;
    const int mq = tid >> 6;     // 0..3
    const float* argb = arg + bb * STRIDE;

    int u_c  = bid;
    int m0_c;
    {
        int ks = u_c / NTILE;
        m0_c = (u_c - ks * NTILE) * MT;
    }

    issue(); CP_COMMIT(); adv();
    issue(); CP_COMMIT(); adv();

    int slot_c = 0;

    for (int g = 0; g < total; g++) {
        CP_WAIT1();
        __syncthreads();

        if (g + 2 < total) issue();
        CP_COMMIT();
        adv();

        // ---- compute stage g: one k16-step, warp tile 32m x 64b ----
        const float* buf = sm + slot_c * SB_FLOATS;
        slot_c = (slot_c == NST - 1) ? 0 : slot_c + 1;

        const float* ca = buf + (2 * quad) * PC + mg * 32 + qid;
        const unsigned* fb = (const unsigned*)(buf + CS_FLOATS) + quad * PFW + qid;

        unsigned b0[8], b1[8];
        #pragma unroll
        for (int nt = 0; nt < 8; nt++) {
            b0[nt] = fb[nt * 8];
            b1[nt] = fb[4 * PFW + nt * 8];
        }

        #pragma unroll
        for (int mt = 0; mt < 2; mt++) {
            const float* cm = ca + mt * 16;
            unsigned a0 = pack_bf16(cm[0],          cm[PC]);
            unsigned a1 = pack_bf16(cm[8],          cm[PC + 8]);
            unsigned a2 = pack_bf16(cm[8 * PC],     cm[9 * PC]);
            unsigned a3 = pack_bf16(cm[8 * PC + 8], cm[9 * PC + 8]);
            #pragma unroll
            for (int nt = 0; nt < 8; nt++)
                MMA_BF16(acc[mt][nt], a0, a1, a2, a3, b0[nt], b1[nt]);
        }

        // ---- unit boundary: 4 write-only passes, 2 mg-slabs each ----
        if ((g & (SPU - 1)) == SPU - 1) {
            #pragma unroll
            for (int p = 0; p < 4; p++) {
                __syncthreads();
                if ((mg >> 1) == p) {
                    int rbase = (mg & 1) * 32;
                    #pragma unroll
                    for (int mt = 0; mt < 2; mt++) {
                        int cr = rbase + mt * 16 + qid;
                        #pragma unroll
                        for (int nt = 0; nt < 8; nt++) {
                            int bc = nt * 8 + 2 * quad;
                            Ds[cr * PD + bc]           = acc[mt][nt][0];
                            Ds[cr * PD + bc + 1]       = acc[mt][nt][1];
                            Ds[(cr + 8) * PD + bc]     = acc[mt][nt][2];
                            Ds[(cr + 8) * PD + bc + 1] = acc[mt][nt][3];
                        }
                    }
                }
                __syncthreads();
                // reduce this 64-row slab: thread (bb, mq) over 16 rows
                #pragma unroll 4
                for (int mm = 0; mm < 16; mm++) {
                    int m = m0_c + p * 64 + mq * 16 + mm;
                    unsigned j = (unsigned)m / 3u;
                    int k = m - 3 * (int)j;
                    float t = Ds[(mq * 16 + mm) * PD + bb] * __ldg(argb + j);
                    if (k == 0) po0 += t;
                    else if (k == 1) po1 += t;
                    else po2 += t;
                }
            }
            __syncthreads();

            #pragma unroll
            for (int mt = 0; mt < 2; mt++)
                #pragma unroll
                for (int nt = 0; nt < 8; nt++)
                    #pragma unroll
                    for (int r = 0; r < 4; r++) acc[mt][nt][r] = 0.0f;

            u_c += GRID;
            if (u_c < NUNITS) {
                int ks = u_c / NTILE;
                m0_c = (u_c - ks * NTILE) * MT;
            }
        }
    }

    // ---- final flush ----
    if (tid < 192) sout[tid] = 0.0f;
    __syncthreads();
    atomicAdd(&sout[bb * 3 + 0], po0);
    atomicAdd(&sout[bb * 3 + 1], po1);
    atomicAdd(&sout[bb * 3 + 2], po2);
    __syncthreads();
    if (tid < 192) atomicAdd(&out[tid], sout[tid]);
}

// ---------------------------------------------------------------------------
extern "C" void kernel_launch(void* const* d_in, const int* in_sizes, int n_in,
                              void* d_out, int out_size) {
    const float* func = (const float*)d_in[0];
    const float* arg  = (const float*)d_in[1];
    const float* cooc = (const float*)d_in[2];
    float* out = (float*)d_out;

    cudaFuncSetAttribute(cooc_mma, cudaFuncAttributeMaxDynamicSharedMemorySize, SMEM_DYN);

    prep_kernel<<<((V / 2) * NB) / 256, 256>>>(func, out);
    cooc_mma<<<GRID, 256, SMEM_DYN>>>(cooc, arg, out);
}

// round 17
// speedup vs baseline: 1.3719x; 1.3719x over previous
#include <cuda_runtime.h>
#include <cstdint>

#define V 8192
#define NB 64
#define M3 24576
#define STRIDE 8194
#define MT 128
#define NTILE 192            // 24576 / 128 m-tiles
#define KS 16                // split-K -> 512 K per unit
#define NUNITS (NTILE * KS)  // 3072
#define GRID 444             // persistent, 3 CTAs/SM
#define KC 32
#define SPU 16               // stages per unit

#define PB 136               // bf16-pair C tile pitch (words): bank-clean
#define PFW 72               // f pair-tile pitch (words)
#define PD 72

#define CB_WORDS (16 * PB)                   // 2176 (16 k2-rows x 128 m)
#define FS_WORDS (16 * PFW)                  // 1152
#define SB_WORDS (CB_WORDS + FS_WORDS)       // 3328
#define DS_OFF   (2 * SB_WORDS)              // 6656 (double buffer)
#define SOUT_OFF (DS_OFF + 32 * PD)          // 8960
#define SMEM_DYN ((SOUT_OFF + 192) * 4)      // 36608 B -> 3 CTAs/SM

#define MMA_BF16(d, a0, a1, a2, a3, b0, b1)                                   \
    asm volatile("mma.sync.aligned.m16n8k16.row.col.f32.bf16.bf16.f32 "       \
        "{%0,%1,%2,%3}, {%4,%5,%6,%7}, {%8,%9}, {%0,%1,%2,%3};"               \
        : "+f"((d)[0]), "+f"((d)[1]), "+f"((d)[2]), "+f"((d)[3])              \
        : "r"(a0), "r"(a1), "r"(a2), "r"(a3), "r"(b0), "r"(b1))

#define CP16(dst_u32, src_gl) \
    asm volatile("cp.async.cg.shared.global [%0], [%1], 16;" :: "r"(dst_u32), "l"(src_gl))
#define CP_COMMIT()  asm volatile("cp.async.commit_group;" ::: "memory")
#define CP_WAIT0()   asm volatile("cp.async.wait_group 0;" ::: "memory")

// f packed as bf16 k-pairs: g_fP[i2*64 + b] = {lo: f[b][2*i2], hi: f[b][2*i2+1]}
__device__ unsigned g_fP[(V / 2) * NB];   // 1 MB, L2-resident

__device__ __forceinline__ unsigned pack_bf16(float lo, float hi) {
    unsigned r;
    asm("cvt.rn.bf16x2.f32 %0, %1, %2;" : "=r"(r) : "f"(hi), "f"(lo));
    return r;
}

// ---------------------------------------------------------------------------
__global__ void prep_kernel(const float* __restrict__ func, float* __restrict__ out) {
    int idx = blockIdx.x * 256 + threadIdx.x;    // < (V/2)*NB = 262144
    int i2 = idx >> 6;
    int b  = idx & 63;
    float lo = func[b * STRIDE + 2 * i2];
    float hi = func[b * STRIDE + 2 * i2 + 1];
    g_fP[idx] = pack_bf16(lo, hi);
    if (idx < NB) {
        const float QI = 1000000000.0f;
        float a1 = func[idx * STRIDE + V];
        float a2 = func[idx * STRIDE + V + 1];
        out[idx * 3 + 0] = a1 * -QI;
        out[idx * 3 + 1] = (1.0f - (1.0f - a1) * (1.0f - a2)) * -QI;
        out[idx * 3 + 2] = 0.0f;
    }
}

// ---------------------------------------------------------------------------
// Persistent bf16 GEMM: producer-side bf16 conversion, bf16 SMEM tiles,
// one __syncthreads per stage, 3 CTAs/SM, mg x bg warp split.
// ---------------------------------------------------------------------------
__global__ __launch_bounds__(256, 3)
void cooc_mma(const float* __restrict__ cooc,
              const float* __restrict__ arg,
              float* __restrict__ out) {
    extern __shared__ unsigned smu[];
    float* Ds   = (float*)(smu + DS_OFF);    // 32 rows x PD
    float* sout = (float*)(smu + SOUT_OFF);

    const int tid  = threadIdx.x;
    const int lane = tid & 31;
    const int wid  = tid >> 5;
    const int mg   = wid & 3;          // m-group: 32 m each
    const int bg   = wid >> 2;         // b-group: 32 b each
    const int quad = lane & 3;
    const int qid  = lane >> 2;
    const int bid  = blockIdx.x;

    const int nu    = 1 + (NUNITS - 1 - bid) / GRID;
    const int total = nu * SPU;

    unsigned smem_base;
    asm("{ .reg .u64 t; cvta.to.shared.u64 t, %1; cvt.u32.u64 %0, t; }"
        : "=r"(smem_base) : "l"(smu));

    const char* fP_g = (const char*)__cvta_generic_to_global(g_fP);

    // C producer slots: 16 pair-rows x 32 col-chunks = 512 -> 2 per thread
    int prr[2], cc[2];
    #pragma unroll
    for (int it = 0; it < 2; it++) {
        int flat = it * 256 + tid;
        prr[it] = flat >> 5;       // pair-row 0..15
        cc[it]  = flat & 31;       // float4 column chunk
    }
    const int f_row = tid >> 4;    // 0..15
    const int f_c16 = tid & 15;

    // -------- issue-stream state (stage s+1) ----
    int u_i  = bid;
    int sl_i = 0;
    int m0_i, k0_i;
    {
        int ks = u_i / NTILE;
        m0_i = (u_i - ks * NTILE) * MT;
        k0_i = ks * (V / KS);
    }

    float4 cr0[2], cr1[2];     // prefetched C rows (pair lo/hi)

    auto ldgC = [&]() {
        #pragma unroll
        for (int it = 0; it < 2; it++) {
            const float* p = cooc + (size_t)(k0_i + 2 * prr[it]) * M3 + m0_i + cc[it] * 4;
            cr0[it] = __ldg((const float4*)p);
            cr1[it] = __ldg((const float4*)(p + M3));
        }
    };
    auto issue_f = [&](int slot) {
        unsigned dst = smem_base + (unsigned)(slot * SB_WORDS + CB_WORDS) * 4;
        const char* src = fP_g + ((size_t)((k0_i >> 1) + f_row) * 64 + f_c16 * 4) * 4;
        CP16(dst + (unsigned)(f_row * PFW + f_c16 * 4) * 4, src);
    };
    auto adv = [&]() {
        if (++sl_i == SPU) {
            sl_i = 0;
            u_i += GRID;
            if (u_i < NUNITS) {
                int ks = u_i / NTILE;
                m0_i = (u_i - ks * NTILE) * MT;
                k0_i = ks * (V / KS);
            }
        } else {
            k0_i += KC;
        }
    };

    float acc[2][4][4];
    #pragma unroll
    for (int mt = 0; mt < 2; mt++)
        #pragma unroll
        for (int nt = 0; nt < 4; nt++)
            #pragma unroll
            for (int r = 0; r < 4; r++) acc[mt][nt][r] = 0.0f;

    float po0 = 0.f, po1 = 0.f, po2 = 0.f;
    const int bb = tid & 63;
    const int mq = tid >> 6;     // 0..3
    const float* argb = arg + bb * STRIDE;

    int u_c  = bid;
    int m0_c;
    {
        int ks = u_c / NTILE;
        m0_c = (u_c - ks * NTILE) * MT;
    }

    // prologue: stage 0 C in regs + f(0) in flight; state -> stage 1
    ldgC();
    issue_f(0);
    CP_COMMIT();
    adv();

    for (int g = 0; g < total; g++) {
        const int pb = g & 1;

        // ---- STS stage g: convert to bf16 pairs, 2 x STS.128 ----
        {
            unsigned cbase = smem_base + (unsigned)(pb * SB_WORDS) * 4;
            #pragma unroll
            for (int it = 0; it < 2; it++) {
                uint4 w;
                w.x = pack_bf16(cr0[it].x, cr1[it].x);
                w.y = pack_bf16(cr0[it].y, cr1[it].y);
                w.z = pack_bf16(cr0[it].z, cr1[it].z);
                w.w = pack_bf16(cr0[it].w, cr1[it].w);
                *(uint4*)((char*)smu + ((size_t)pb * SB_WORDS + prr[it] * PB + cc[it] * 4) * 4) = w;
            }
            (void)cbase;
        }

        CP_WAIT0();                 // f(g) complete (issued last iteration)
        __syncthreads();            // C(g)+f(g) visible; all warps past compute(g-1)

        // ---- issue stage g+1 (safe: everyone left (g+1)-parity buffers) ----
        if (g + 1 < total) {
            ldgC();
            issue_f((g + 1) & 1);
        }
        CP_COMMIT();
        adv();

        // ---- compute stage g: warp tile 32m x 32b, full 32-k ----
        const unsigned* cb = smu + pb * SB_WORDS;
        const unsigned* fw = smu + pb * SB_WORDS + CB_WORDS;

        #pragma unroll
        for (int kk = 0; kk < 2; kk++) {
            const unsigned* ca = cb + (kk * 8 + quad) * PB + mg * 32 + qid;
            const unsigned* fb = fw + (kk * 8 + quad) * PFW + bg * 32 + qid;

            unsigned b0[4], b1[4];
            #pragma unroll
            for (int nt = 0; nt < 4; nt++) {
                b0[nt] = fb[nt * 8];
                b1[nt] = fb[4 * PFW + nt * 8];
            }

            #pragma unroll
            for (int mt = 0; mt < 2; mt++) {
                const unsigned* cm = ca + mt * 16;
                unsigned a0 = cm[0];
                unsigned a1 = cm[8];
                unsigned a2 = cm[4 * PB];
                unsigned a3 = cm[4 * PB + 8];
                #pragma unroll
                for (int nt = 0; nt < 4; nt++)
                    MMA_BF16(acc[mt][nt], a0, a1, a2, a3, b0[nt], b1[nt]);
            }
        }

        // ---- unit boundary: 4 write-only passes + reduce ----
        if ((g & (SPU - 1)) == SPU - 1) {
            #pragma unroll
            for (int p = 0; p < 4; p++) {
                __syncthreads();
                if (mg == p) {
                    #pragma unroll
                    for (int mt = 0; mt < 2; mt++) {
                        int cr = mt * 16 + qid;
                        #pragma unroll
                        for (int nt = 0; nt < 4; nt++) {
                            int bc = bg * 32 + nt * 8 + 2 * quad;
                            Ds[cr * PD + bc]           = acc[mt][nt][0];
                            Ds[cr * PD + bc + 1]       = acc[mt][nt][1];
                            Ds[(cr + 8) * PD + bc]     = acc[mt][nt][2];
                            Ds[(cr + 8) * PD + bc + 1] = acc[mt][nt][3];
                        }
                    }
                }
                __syncthreads();
                #pragma unroll 4
                for (int mm = 0; mm < 8; mm++) {
                    int m = m0_c + p * 32 + mq * 8 + mm;
                    unsigned j = (unsigned)m / 3u;
                    int k = m - 3 * (int)j;
                    float t = Ds[(mq * 8 + mm) * PD + bb] * __ldg(argb + j);
                    if (k == 0) po0 += t;
                    else if (k == 1) po1 += t;
                    else po2 += t;
                }
            }
            __syncthreads();

            #pragma unroll
            for (int mt = 0; mt < 2; mt++)
                #pragma unroll
                for (int nt = 0; nt < 4; nt++)
                    #pragma unroll
                    for (int r = 0; r < 4; r++) acc[mt][nt][r] = 0.0f;

            u_c += GRID;
            if (u_c < NUNITS) {
                int ks = u_c / NTILE;
                m0_c = (u_c - ks * NTILE) * MT;
            }
        }
    }

    // ---- final flush ----
    if (tid < 192) sout[tid] = 0.0f;
    __syncthreads();
    atomicAdd(&sout[bb * 3 + 0], po0);
    atomicAdd(&sout[bb * 3 + 1], po1);
    atomicAdd(&sout[bb * 3 + 2], po2);
    __syncthreads();
    if (tid < 192) atomicAdd(&out[tid], sout[tid]);
}

// ---------------------------------------------------------------------------
extern "C" void kernel_launch(void* const* d_in, const int* in_sizes, int n_in,
                              void* d_out, int out_size) {
    const float* func = (const float*)d_in[0];
    const float* arg  = (const float*)d_in[1];
    const float* cooc = (const float*)d_in[2];
    float* out = (float*)d_out;

    cudaFuncSetAttribute(cooc_mma, cudaFuncAttributeMaxDynamicSharedMemorySize, SMEM_DYN);

    prep_kernel<<<((V / 2) * NB) / 256, 256>>>(func, out);
    cooc_mma<<<GRID, 256, SMEM_DYN>>>(cooc, arg, out);
}